// round 10
// baseline (speedup 1.0000x reference)
#include <cuda_runtime.h>

#define TT 512
#define BB 1024
#define NN 64
#define GRID 512   // 2 batches per 128-thread CTA (2 warps per batch)
#define PD 4

__device__ float g_partial[BB];
__device__ int g_count = 0;

typedef unsigned long long ull;

// ---- packed f32x2 helpers (Blackwell) ----
__device__ __forceinline__ ull pack2(float x, float y) {
    ull r; asm("mov.b64 %0, {%1, %2};" : "=l"(r) : "f"(x), "f"(y)); return r;
}
__device__ __forceinline__ void unpack2(ull v, float& x, float& y) {
    asm("mov.b64 {%0, %1}, %2;" : "=f"(x), "=f"(y) : "l"(v));
}
__device__ __forceinline__ ull fma2(ull a, ull b, ull c) {
    ull d; asm("fma.rn.f32x2 %0, %1, %2, %3;" : "=l"(d) : "l"(a), "l"(b), "l"(c)); return d;
}
__device__ __forceinline__ ull add2(ull a, ull b) {
    ull d; asm("add.rn.f32x2 %0, %1, %2;" : "=l"(d) : "l"(a), "l"(b)); return d;
}

// cp.async 4B: no dest register -> ptxas cannot sink it; wait_group enforces distance
__device__ __forceinline__ void cp_async4(unsigned smem_addr, const void* gptr) {
    asm volatile("cp.async.ca.shared.global [%0], [%1], 4;" :: "r"(smem_addr), "l"(gptr));
}
__device__ __forceinline__ void cp_commit() {
    asm volatile("cp.async.commit_group;");
}
__device__ __forceinline__ void cp_wait3() {
    asm volatile("cp.async.wait_group %0;" :: "n"(PD - 1));
}
__device__ __forceinline__ void pair_bar(int id) {
    asm volatile("bar.sync %0, 64;" :: "r"(id) : "memory");
}

__device__ __forceinline__ int seq_len(const void* mask_raw, int mmode, int b, int lane) {
    const unsigned char* m8 = (const unsigned char*)mask_raw;
    const int* m32 = (const int*)mask_raw;
    const float* mf = (const float*)mask_raw;
    int len = 0;
    if (mmode == 0) {
#pragma unroll 4
        for (int t = lane; t < TT; t += 32) len += (m8[(size_t)t * BB + b] != 0);
    } else if (mmode == 1) {
#pragma unroll 4
        for (int t = lane; t < TT; t += 32) len += (m32[(size_t)t * BB + b] != 0);
    } else {
#pragma unroll 4
        for (int t = lane; t < TT; t += 32) len += (mf[(size_t)t * BB + b] != 0.0f);
    }
#pragma unroll
    for (int o = 16; o; o >>= 1) len += __shfl_xor_sync(0xffffffffu, len, o);
    return len;
}

// gold-path score; result valid on lane 0 (run by one full warp)
__device__ __forceinline__ float gold_score(
    const float* __restrict__ emit, const float* __restrict__ trans,
    const float* __restrict__ strans, const float* __restrict__ etrans,
    const void* __restrict__ traw, int tmode, int b, int len, int lane)
{
    const int* t32 = (const int*)traw;
    const long long* t64 = (const long long*)traw;
    float sc = 0.f;
    for (int i = lane; i < len; i += 32) {
        size_t idx = (size_t)i * BB + b;
        int tg = tmode ? (int)t64[idx] : t32[idx];
        sc += emit[idx * NN + tg];
        if (i > 0) {
            size_t p = (size_t)(i - 1) * BB + b;
            int pg = tmode ? (int)t64[p] : t32[p];
            sc += trans[pg * NN + tg];
        }
    }
#pragma unroll
    for (int o = 16; o; o >>= 1) sc += __shfl_xor_sync(0xffffffffu, sc, o);
    if (lane == 0) {
        int tg0 = tmode ? (int)t64[b] : t32[b];
        size_t li = (size_t)(len - 1) * BB + b;
        int tgl = tmode ? (int)t64[li] : t32[li];
        sc += strans[tg0] + etrans[tgl];
    }
    return sc;
}

__global__ void __launch_bounds__(128, 4) crf_fused_kernel(
    const float* __restrict__ emit,
    const float* __restrict__ trans,
    const float* __restrict__ strans,
    const float* __restrict__ etrans,
    const void* __restrict__ target_raw,
    const void* __restrict__ mask_raw,
    float* __restrict__ out)
{
    const int lane = threadIdx.x & 31;
    const int w = threadIdx.x >> 5;
    const int q = w >> 1;                 // pair id within CTA (0,1)
    const int half = w & 1;               // which 32-state half this warp owns
    const int b = blockIdx.x * 2 + q;     // GRID*2 == BB
    const int k = half * 32 + lane;       // this lane's state

    // double-buffered full-state broadcast: 64 floats per pair per parity (16B-aligned)
    __shared__ __align__(16) float vbuf[2][2][NN];
    __shared__ float stagef[4][PD][32];   // cp.async emit staging ring (per warp)
    __shared__ float wred[2][2];          // pair-combine for final logsumexp

    // ---- dtype self-detection (mask row 0 all-True since lengths >= 1) ----
    const unsigned char* m8 = (const unsigned char*)mask_raw;
    int mmode;  // 0 = u8, 1 = i32, 2 = f32
    if (m8[0] == 1 && m8[1] == 1)      mmode = 0;
    else if (m8[0] == 1)               mmode = 1;
    else                               mmode = 2;

    const int* t32p = (const int*)target_raw;
    int oddbits = 0;
#pragma unroll
    for (int i = 1; i < 16; i += 2) oddbits |= t32p[i];
    const int tmode = (oddbits == 0) ? 1 : 0;  // 1 = int64, 0 = int32

    // E column for this lane's state, packed over j-pairs:
    //   Ecol[p] = (exp(trans[2p][k]), exp(trans[2p+1][k]))   -> 32 ull = 64 regs
    ull Ecol[32];
#pragma unroll
    for (int p = 0; p < 32; p++) {
        float t0 = trans[(2 * p) * NN + k];
        float t1 = trans[(2 * p + 1) * NN + k];
        Ecol[p] = pack2(__expf(t0), __expf(t1));
    }

    const int len = seq_len(mask_raw, mmode, b, lane);

    // init: alpha(0)_k = strans[k] + emit[0][b][k]; common offset C0 = alpha(0)_0
    const float C0 = strans[0] + emit[(size_t)b * NN];
    float ia = strans[k] + emit[(size_t)b * NN + k];
    float v = __expf(ia - C0);            // linear-domain state for this lane's k
    int stotal = 0;

    // staging slot addresses for cp.async (4B per lane)
    unsigned stg_addr[PD];
#pragma unroll
    for (int j = 0; j < PD; j++)
        stg_addr[j] = (unsigned)__cvta_generic_to_shared(&stagef[w][j][lane]);

    // prologue: fill ring with steps t = 1..PD (clamped), one commit group each
#pragma unroll
    for (int j = 0; j < PD; j++) {
        cp_async4(stg_addr[j], &emit[((size_t)min(1 + j, TT - 1) * BB + b) * NN + k]);
        cp_commit();
    }

    const int barid = 1 + q;

    for (int t = 1; t < len; t++) {
        const int slot = (t - 1) & (PD - 1);
        cp_wait3();                                  // slot for step t complete
        float e = stagef[w][slot][lane];
        cp_async4(stg_addr[slot], &emit[((size_t)min(t + PD, TT - 1) * BB + b) * NN + k]);
        cp_commit();

        // publish this half's v, sync pair, read full 64-state vector
        const int par = t & 1;
        vbuf[par][q][k] = v;                         // STS.32
        pair_bar(barid);
        const ulonglong2* vv = reinterpret_cast<const ulonglong2*>(vbuf[par][q]);

        // c_k = sum_p dot(vpair_p, Ecol[p])  — 32 fma2, 4 accumulators
        ulonglong2 q0 = vv[0];                       // floats 0..3 (vpairs 0,1)
        // normalization reference = state 0 of v(t-1) = low float of q0.x (free)
        float rref; { float hi; unpack2(q0.x, rref, hi); (void)hi; }
        int sexp = ((__float_as_int(rref) >> 23) & 0xFF) - 127;
        stotal += sexp;
        float scl = __int_as_float((127 - sexp) << 23);
        float m = __expf(e) * scl;                   // off the fma critical path

        ull c0 = 0, c1 = 0, c2 = 0, c3 = 0;
        {
            ulonglong2 q1 = vv[1];
            c0 = fma2(q0.x, Ecol[0], c0);
            c1 = fma2(q0.y, Ecol[1], c1);
            c2 = fma2(q1.x, Ecol[2], c2);
            c3 = fma2(q1.y, Ecol[3], c3);
        }
#pragma unroll
        for (int p = 4; p < 32; p += 4) {
            ulonglong2 u0 = vv[p / 2];
            ulonglong2 u1 = vv[p / 2 + 1];
            c0 = fma2(u0.x, Ecol[p],     c0);
            c1 = fma2(u0.y, Ecol[p + 1], c1);
            c2 = fma2(u1.x, Ecol[p + 2], c2);
            c3 = fma2(u1.y, Ecol[p + 3], c3);
        }
        float cx, cy;
        unpack2(add2(add2(c0, c1), add2(c2, c3)), cx, cy);
        v = (cx + cy) * m;
    }

    // logZ_b = C0 + ln2*stotal + log( sum_k v_k * exp(etrans_k) )
    float wpart = v * __expf(etrans[k]);
#pragma unroll
    for (int o = 16; o; o >>= 1) wpart += __shfl_xor_sync(0xffffffffu, wpart, o);
    if (lane == 0) wred[q][half] = wpart;
    pair_bar(barid);

    if (half == 0) {
        float wsum = wred[q][0] + wred[q][1];
        float logZ = C0 + 0.6931471805599453f * (float)stotal + __logf(wsum);
        float sc = gold_score(emit, trans, strans, etrans, target_raw, tmode, b, len, lane);
        if (lane == 0) g_partial[b] = logZ - sc;
    }

    // ---- last-CTA-done deterministic reduction ----
    __shared__ float rsh[128];
    __shared__ int islast;
    __threadfence();
    __syncthreads();
    if (threadIdx.x == 0)
        islast = (atomicAdd(&g_count, 1) == GRID - 1);
    __syncthreads();
    if (islast) {
        __threadfence();
        float s = 0.f;
#pragma unroll
        for (int i = 0; i < BB / 128; i++)          // fixed order: deterministic
            s += g_partial[threadIdx.x + i * 128];
        rsh[threadIdx.x] = s;
        __syncthreads();
        for (int off = 64; off > 0; off >>= 1) {
            if (threadIdx.x < off) rsh[threadIdx.x] += rsh[threadIdx.x + off];
            __syncthreads();
        }
        if (threadIdx.x == 0) {
            out[0] = rsh[0] * (1.0f / BB);
            g_count = 0;                            // reset for next graph replay
        }
    }
}

extern "C" void kernel_launch(void* const* d_in, const int* in_sizes, int n_in,
                              void* d_out, int out_size) {
    const float* emit   = (const float*)d_in[0];
    const float* trans  = (const float*)d_in[1];
    const float* strans = (const float*)d_in[2];
    const float* etrans = (const float*)d_in[3];
    const void* target  = d_in[4];
    const void* mask    = d_in[5];

    crf_fused_kernel<<<GRID, 128>>>(emit, trans, strans, etrans, target, mask,
                                    (float*)d_out);
}

// round 11
// speedup vs baseline: 1.2921x; 1.2921x over previous
#include <cuda_runtime.h>

#define TT 512
#define BB 1024
#define NN 64
#define GRID 256      // main kernel: 256 CTAs x 4 warps = 512 pairs x 2 warps
#define PD 4

__device__ float g_partial[BB];
__device__ int g_len[BB];
__device__ int g_pairs[2][BB / 2];
__device__ int g_count = 0;

typedef unsigned long long ull;

// ---- packed f32x2 helpers (Blackwell) ----
__device__ __forceinline__ ull pack2(float x, float y) {
    ull r; asm("mov.b64 %0, {%1, %2};" : "=l"(r) : "f"(x), "f"(y)); return r;
}
__device__ __forceinline__ void unpack2(ull v, float& x, float& y) {
    asm("mov.b64 {%0, %1}, %2;" : "=f"(x), "=f"(y) : "l"(v));
}
__device__ __forceinline__ ull fma2(ull a, ull b, ull c) {
    ull d; asm("fma.rn.f32x2 %0, %1, %2, %3;" : "=l"(d) : "l"(a), "l"(b), "l"(c)); return d;
}
__device__ __forceinline__ ull add2(ull a, ull b) {
    ull d; asm("add.rn.f32x2 %0, %1, %2;" : "=l"(d) : "l"(a), "l"(b)); return d;
}

__device__ __forceinline__ void cp_async4(unsigned smem_addr, const void* gptr) {
    asm volatile("cp.async.ca.shared.global [%0], [%1], 4;" :: "r"(smem_addr), "l"(gptr));
}
__device__ __forceinline__ void cp_commit() {
    asm volatile("cp.async.commit_group;");
}
__device__ __forceinline__ void cp_wait3() {
    asm volatile("cp.async.wait_group %0;" :: "n"(PD - 1));
}
__device__ __forceinline__ void cp_wait0() {
    asm volatile("cp.async.wait_group 0;");
}
__device__ __forceinline__ void pair_bar(int id) {
    asm volatile("bar.sync %0, 64;" :: "r"(id) : "memory");
}

// ---------------- kernel 1: per-batch sequence lengths ----------------
__global__ void __launch_bounds__(128) len_kernel(const void* __restrict__ mask_raw) {
    const int lane = threadIdx.x & 31;
    const int b = blockIdx.x * 4 + (threadIdx.x >> 5);

    const unsigned char* m8 = (const unsigned char*)mask_raw;
    const int* m32 = (const int*)mask_raw;
    const float* mf = (const float*)mask_raw;
    int mmode;  // 0 = u8, 1 = i32, 2 = f32 (mask row 0 all-True since lengths >= 1)
    if (m8[0] == 1 && m8[1] == 1)      mmode = 0;
    else if (m8[0] == 1)               mmode = 1;
    else                               mmode = 2;

    int len = 0;
    if (mmode == 0) {
#pragma unroll 4
        for (int t = lane; t < TT; t += 32) len += (m8[(size_t)t * BB + b] != 0);
    } else if (mmode == 1) {
#pragma unroll 4
        for (int t = lane; t < TT; t += 32) len += (m32[(size_t)t * BB + b] != 0);
    } else {
#pragma unroll 4
        for (int t = lane; t < TT; t += 32) len += (mf[(size_t)t * BB + b] != 0.0f);
    }
#pragma unroll
    for (int o = 16; o; o >>= 1) len += __shfl_xor_sync(0xffffffffu, len, o);
    if (lane == 0) g_len[b] = len;
}

// ------------- kernel 2: bitonic sort by length; complement pairing -------------
__global__ void __launch_bounds__(BB) sort_kernel() {
    __shared__ int a[BB];
    const int tid = threadIdx.x;
    a[tid] = (g_len[tid] << 11) | tid;        // len<=512 (10 bits) | idx (10 bits)
    __syncthreads();
    for (int k = 2; k <= BB; k <<= 1) {
        for (int j = k >> 1; j > 0; j >>= 1) {
            int ixj = tid ^ j;
            if (ixj > tid) {
                bool up = (tid & k) == 0;
                int x = a[tid], y = a[ixj];
                if ((x > y) == up) { a[tid] = y; a[ixj] = x; }
            }
            __syncthreads();
        }
    }
    if (tid < BB / 2) {
        g_pairs[0][tid] = a[tid] & 0x7FF;               // short batch
        g_pairs[1][tid] = a[BB - 1 - tid] & 0x7FF;      // long batch (sum ~= const)
    }
}

// ---------------- kernel 3: fused forward + score + reduce ----------------
__global__ void __launch_bounds__(128, 2) crf_fused_kernel(
    const float* __restrict__ emit,
    const float* __restrict__ trans,
    const float* __restrict__ strans,
    const float* __restrict__ etrans,
    const void* __restrict__ target_raw,
    float* __restrict__ out)
{
    const int lane = threadIdx.x & 31;
    const int w = threadIdx.x >> 5;
    const int q = w >> 1;                 // pair id within CTA
    const int half = w & 1;
    const int pairid = blockIdx.x * 2 + q;
    const int k = half * 32 + lane;       // this lane's state
    const int gtid = half * 32 + lane;    // 0..63 across the pair

    __shared__ __align__(16) float vbuf[2][2][NN];    // double-buffered state exchange
    __shared__ float stagef[4][PD][32];               // cp.async emit staging (per warp)
    __shared__ float wred[2][2], sred[2][2];

    const int* t32p = (const int*)target_raw;
    int oddbits = 0;
#pragma unroll
    for (int i = 1; i < 16; i += 2) oddbits |= t32p[i];
    const int tmode = (oddbits == 0) ? 1 : 0;  // 1 = int64, 0 = int32
    const long long* t64p = (const long long*)target_raw;

    // E column for this lane's state, packed over j-pairs (64 regs)
    ull Ecol[32];
#pragma unroll
    for (int p = 0; p < 32; p++) {
        float t0 = trans[(2 * p) * NN + k];
        float t1 = trans[(2 * p + 1) * NN + k];
        Ecol[p] = pack2(__expf(t0), __expf(t1));
    }

    unsigned stg_addr[PD];
#pragma unroll
    for (int j = 0; j < PD; j++)
        stg_addr[j] = (unsigned)__cvta_generic_to_shared(&stagef[w][j][lane]);

    const int barid = 1 + q;
    const float eet = __expf(etrans[k]);

    for (int ph = 0; ph < 2; ph++) {
        const int b = g_pairs[ph][pairid];
        const int len = g_len[b];

        // init: alpha(0)_k = strans[k] + emit[0][b][k]; offset C0 = alpha(0)_0
        const float C0 = strans[0] + emit[(size_t)b * NN];
        float v = __expf(strans[k] + emit[(size_t)b * NN + k] - C0);
        int stotal = 0;

        cp_wait0();                                  // drain ring before reuse
        __syncwarp();
#pragma unroll
        for (int j = 0; j < PD; j++) {
            cp_async4(stg_addr[j], &emit[((size_t)min(1 + j, TT - 1) * BB + b) * NN + k]);
            cp_commit();
        }

        for (int t = 1; t < len; t++) {
            const int slot = (t - 1) & (PD - 1);
            cp_wait3();
            float e = stagef[w][slot][lane];
            cp_async4(stg_addr[slot], &emit[((size_t)min(t + PD, TT - 1) * BB + b) * NN + k]);
            cp_commit();

            const int par = t & 1;
            vbuf[par][q][k] = v;
            pair_bar(barid);
            const ulonglong2* vv = reinterpret_cast<const ulonglong2*>(vbuf[par][q]);

            ulonglong2 q0 = vv[0];
            float rref; { float hi; unpack2(q0.x, rref, hi); (void)hi; }
            int sexp = ((__float_as_int(rref) >> 23) & 0xFF) - 127;
            stotal += sexp;
            float scl = __int_as_float((127 - sexp) << 23);
            float m = __expf(e) * scl;

            ull c0 = 0, c1 = 0, c2 = 0, c3 = 0;
            {
                ulonglong2 q1 = vv[1];
                c0 = fma2(q0.x, Ecol[0], c0);
                c1 = fma2(q0.y, Ecol[1], c1);
                c2 = fma2(q1.x, Ecol[2], c2);
                c3 = fma2(q1.y, Ecol[3], c3);
            }
#pragma unroll
            for (int p = 4; p < 32; p += 4) {
                ulonglong2 u0 = vv[p / 2];
                ulonglong2 u1 = vv[p / 2 + 1];
                c0 = fma2(u0.x, Ecol[p],     c0);
                c1 = fma2(u0.y, Ecol[p + 1], c1);
                c2 = fma2(u1.x, Ecol[p + 2], c2);
                c3 = fma2(u1.y, Ecol[p + 3], c3);
            }
            float cx, cy;
            unpack2(add2(add2(c0, c1), add2(c2, c3)), cx, cy);
            v = (cx + cy) * m;
        }

        // logZ partial
        float wpart = v * eet;
#pragma unroll
        for (int o = 16; o; o >>= 1) wpart += __shfl_xor_sync(0xffffffffu, wpart, o);

        // gold score: both warps, 64-lane strided over timesteps
        float sc = 0.f;
        for (int i = gtid; i < len; i += 64) {
            size_t idx = (size_t)i * BB + b;
            int tg = tmode ? (int)t64p[idx] : t32p[idx];
            sc += emit[idx * NN + tg];
            if (i > 0) {
                size_t p = (size_t)(i - 1) * BB + b;
                int pg = tmode ? (int)t64p[p] : t32p[p];
                sc += trans[pg * NN + tg];
            }
        }
#pragma unroll
        for (int o = 16; o; o >>= 1) sc += __shfl_xor_sync(0xffffffffu, sc, o);

        if (lane == 0) { wred[q][half] = wpart; sred[q][half] = sc; }
        pair_bar(barid);
        if (half == 0 && lane == 0) {
            float wsum = wred[q][0] + wred[q][1];
            float logZ = C0 + 0.6931471805599453f * (float)stotal + __logf(wsum);
            int tg0 = tmode ? (int)t64p[b] : t32p[b];
            size_t li = (size_t)(len - 1) * BB + b;
            int tgl = tmode ? (int)t64p[li] : t32p[li];
            float score = sred[q][0] + sred[q][1] + strans[tg0] + etrans[tgl];
            g_partial[b] = logZ - score;
        }
        pair_bar(barid);   // vbuf/wred safe to reuse in next phase
    }

    // ---- last-CTA-done deterministic reduction ----
    __shared__ float rsh[128];
    __shared__ int islast;
    __threadfence();
    __syncthreads();
    if (threadIdx.x == 0)
        islast = (atomicAdd(&g_count, 1) == GRID - 1);
    __syncthreads();
    if (islast) {
        __threadfence();
        float s = 0.f;
#pragma unroll
        for (int i = 0; i < BB / 128; i++)          // fixed order: deterministic
            s += g_partial[threadIdx.x + i * 128];
        rsh[threadIdx.x] = s;
        __syncthreads();
        for (int off = 64; off > 0; off >>= 1) {
            if (threadIdx.x < off) rsh[threadIdx.x] += rsh[threadIdx.x + off];
            __syncthreads();
        }
        if (threadIdx.x == 0) {
            out[0] = rsh[0] * (1.0f / BB);
            g_count = 0;                            // reset for next graph replay
        }
    }
}

extern "C" void kernel_launch(void* const* d_in, const int* in_sizes, int n_in,
                              void* d_out, int out_size) {
    const float* emit   = (const float*)d_in[0];
    const float* trans  = (const float*)d_in[1];
    const float* strans = (const float*)d_in[2];
    const float* etrans = (const float*)d_in[3];
    const void* target  = d_in[4];
    const void* mask    = d_in[5];

    len_kernel<<<BB / 4, 128>>>(mask);
    sort_kernel<<<1, BB>>>();
    crf_fused_kernel<<<GRID, 128>>>(emit, trans, strans, etrans, target,
                                    (float*)d_out);
}

// round 12
// speedup vs baseline: 1.4581x; 1.1285x over previous
#include <cuda_runtime.h>

#define TT 512
#define BB 1024
#define NN 64
#define GRID 512      // main kernel: one pair (2 batches) per 64-thread CTA
#define PD 4

__device__ float g_partial[BB];
__device__ int g_len[BB];
__device__ int g_pairs[2][BB / 2];
__device__ int g_count = 0;

typedef unsigned long long ull;

// ---- packed f32x2 helpers (Blackwell) ----
__device__ __forceinline__ ull pack2(float x, float y) {
    ull r; asm("mov.b64 %0, {%1, %2};" : "=l"(r) : "f"(x), "f"(y)); return r;
}
__device__ __forceinline__ void unpack2(ull v, float& x, float& y) {
    asm("mov.b64 {%0, %1}, %2;" : "=f"(x), "=f"(y) : "l"(v));
}
__device__ __forceinline__ ull fma2(ull a, ull b, ull c) {
    ull d; asm("fma.rn.f32x2 %0, %1, %2, %3;" : "=l"(d) : "l"(a), "l"(b), "l"(c)); return d;
}
__device__ __forceinline__ ull add2(ull a, ull b) {
    ull d; asm("add.rn.f32x2 %0, %1, %2;" : "=l"(d) : "l"(a), "l"(b)); return d;
}

__device__ __forceinline__ void cp_async4(unsigned smem_addr, const void* gptr) {
    asm volatile("cp.async.ca.shared.global [%0], [%1], 4;" :: "r"(smem_addr), "l"(gptr));
}
__device__ __forceinline__ void cp_commit() {
    asm volatile("cp.async.commit_group;");
}
__device__ __forceinline__ void cp_wait3() {
    asm volatile("cp.async.wait_group %0;" :: "n"(PD - 1));
}
__device__ __forceinline__ void cp_wait0() {
    asm volatile("cp.async.wait_group 0;");
}

// ---------------- kernel 1: per-batch sequence lengths ----------------
__global__ void __launch_bounds__(128) len_kernel(const void* __restrict__ mask_raw) {
    const int lane = threadIdx.x & 31;
    const int b = blockIdx.x * 4 + (threadIdx.x >> 5);

    const unsigned char* m8 = (const unsigned char*)mask_raw;
    const int* m32 = (const int*)mask_raw;
    const float* mf = (const float*)mask_raw;
    int mmode;  // 0 = u8, 1 = i32, 2 = f32 (mask row 0 all-True since lengths >= 1)
    if (m8[0] == 1 && m8[1] == 1)      mmode = 0;
    else if (m8[0] == 1)               mmode = 1;
    else                               mmode = 2;

    int len = 0;
    if (mmode == 0) {
#pragma unroll 4
        for (int t = lane; t < TT; t += 32) len += (m8[(size_t)t * BB + b] != 0);
    } else if (mmode == 1) {
#pragma unroll 4
        for (int t = lane; t < TT; t += 32) len += (m32[(size_t)t * BB + b] != 0);
    } else {
#pragma unroll 4
        for (int t = lane; t < TT; t += 32) len += (mf[(size_t)t * BB + b] != 0.0f);
    }
#pragma unroll
    for (int o = 16; o; o >>= 1) len += __shfl_xor_sync(0xffffffffu, len, o);
    if (lane == 0) g_len[b] = len;
}

// ------------- kernel 2: bitonic sort by length; complement pairing -------------
__global__ void __launch_bounds__(BB) sort_kernel() {
    __shared__ int a[BB];
    const int tid = threadIdx.x;
    a[tid] = (g_len[tid] << 11) | tid;        // len<=512 (10 bits) | idx (10 bits)
    __syncthreads();
    for (int k = 2; k <= BB; k <<= 1) {
        for (int j = k >> 1; j > 0; j >>= 1) {
            int ixj = tid ^ j;
            if (ixj > tid) {
                bool up = (tid & k) == 0;
                int x = a[tid], y = a[ixj];
                if ((x > y) == up) { a[tid] = y; a[ixj] = x; }
            }
            __syncthreads();
        }
    }
    if (tid < BB / 2) {
        g_pairs[0][tid] = a[tid] & 0x7FF;               // short batch
        g_pairs[1][tid] = a[BB - 1 - tid] & 0x7FF;      // long batch (sum ~= const)
    }
}

// ---------------- kernel 3: fused forward + score + reduce ----------------
__global__ void __launch_bounds__(64, 8) crf_fused_kernel(
    const float* __restrict__ emit,
    const float* __restrict__ trans,
    const float* __restrict__ strans,
    const float* __restrict__ etrans,
    const void* __restrict__ target_raw,
    float* __restrict__ out)
{
    const int tid = threadIdx.x;          // 0..63
    const int lane = tid & 31;
    const int w = tid >> 5;               // which 32-state half this warp owns
    const int k = tid;                    // this lane's state (0..63)
    const int pairid = blockIdx.x;

    __shared__ __align__(16) float vbuf[2][NN];   // double-buffered state exchange
    __shared__ float stagef[2][PD][32];           // cp.async emit staging (per warp)
    __shared__ float wred[2], sred[2];

    const int* t32p = (const int*)target_raw;
    int oddbits = 0;
#pragma unroll
    for (int i = 1; i < 16; i += 2) oddbits |= t32p[i];
    const int tmode = (oddbits == 0) ? 1 : 0;  // 1 = int64, 0 = int32
    const long long* t64p = (const long long*)target_raw;

    // E column for this lane's state, packed over j-pairs (64 regs)
    ull Ecol[32];
#pragma unroll
    for (int p = 0; p < 32; p++) {
        float t0 = trans[(2 * p) * NN + k];
        float t1 = trans[(2 * p + 1) * NN + k];
        Ecol[p] = pack2(__expf(t0), __expf(t1));
    }

    unsigned stg_addr[PD];
#pragma unroll
    for (int j = 0; j < PD; j++)
        stg_addr[j] = (unsigned)__cvta_generic_to_shared(&stagef[w][j][lane]);

    const float eet = __expf(etrans[k]);
    const size_t TS = (size_t)BB * NN;    // emit stride per timestep (floats)

#define STEP_BODY(SLOT, PAR, TCUR)                                              \
    {                                                                           \
        cp_wait3();                                                             \
        float e = stagef[w][SLOT][lane];                                        \
        cp_async4(stg_addr[SLOT], pf);                                          \
        cp_commit();                                                            \
        if ((TCUR) < TT - 1 - PD) pf += TS;                                     \
        vbuf[PAR][k] = v;                                                       \
        __syncthreads();                                                        \
        const ulonglong2* vv = reinterpret_cast<const ulonglong2*>(vbuf[PAR]);  \
        ulonglong2 q0 = vv[0];                                                  \
        float rref, hi_; unpack2(q0.x, rref, hi_); (void)hi_;                   \
        int sexp = ((__float_as_int(rref) >> 23) & 0xFF) - 127;                 \
        stotal += sexp;                                                         \
        float scl = __int_as_float((127 - sexp) << 23);                         \
        float m = __expf(e) * scl;                                              \
        ull c0 = 0, c1 = 0, c2 = 0, c3 = 0;                                     \
        {                                                                       \
            ulonglong2 q1 = vv[1];                                              \
            c0 = fma2(q0.x, Ecol[0], c0);                                       \
            c1 = fma2(q0.y, Ecol[1], c1);                                       \
            c2 = fma2(q1.x, Ecol[2], c2);                                       \
            c3 = fma2(q1.y, Ecol[3], c3);                                       \
        }                                                                       \
        _Pragma("unroll")                                                       \
        for (int p = 4; p < 32; p += 4) {                                       \
            ulonglong2 u0 = vv[p / 2], u1 = vv[p / 2 + 1];                      \
            c0 = fma2(u0.x, Ecol[p],     c0);                                   \
            c1 = fma2(u0.y, Ecol[p + 1], c1);                                   \
            c2 = fma2(u1.x, Ecol[p + 2], c2);                                   \
            c3 = fma2(u1.y, Ecol[p + 3], c3);                                   \
        }                                                                       \
        float cx, cy;                                                           \
        unpack2(add2(add2(c0, c1), add2(c2, c3)), cx, cy);                      \
        v = (cx + cy) * m;                                                      \
    }

    for (int ph = 0; ph < 2; ph++) {
        const int b = g_pairs[ph][pairid];
        const int len = g_len[b];
        const float* bp = emit + (size_t)b * NN + k;

        // init: alpha(0)_k = strans[k] + emit[0][b][k]; offset C0 = alpha(0)_0
        const float C0 = strans[0] + emit[(size_t)b * NN];
        float v = __expf(strans[k] + emit[(size_t)b * NN + k] - C0);
        int stotal = 0;

        cp_wait0();                                  // drain ring before reuse
        __syncthreads();
#pragma unroll
        for (int j = 0; j < PD; j++) {
            cp_async4(stg_addr[j], bp + (size_t)min(1 + j, TT - 1) * TS);
            cp_commit();
        }
        const float* pf = bp + (size_t)min(PD + 1, TT - 1) * TS;  // fetch target at t=1

        int t = 1;
        for (; t + 4 <= len; t += 4) {               // t = 1 mod 4: slots 0..3, par 1,0,1,0
            STEP_BODY(0, 1, t);
            STEP_BODY(1, 0, t + 1);
            STEP_BODY(2, 1, t + 2);
            STEP_BODY(3, 0, t + 3);
        }
        for (; t < len; t++) {
            const int slot = (t - 1) & 3, par = t & 1;
            STEP_BODY(slot, par, t);
        }

        // logZ partial
        float wpart = v * eet;
#pragma unroll
        for (int o = 16; o; o >>= 1) wpart += __shfl_xor_sync(0xffffffffu, wpart, o);

        // gold score: 64-lane strided over timesteps
        float sc = 0.f;
        for (int i = tid; i < len; i += 64) {
            size_t idx = (size_t)i * BB + b;
            int tg = tmode ? (int)t64p[idx] : t32p[idx];
            sc += emit[idx * NN + tg];
            if (i > 0) {
                size_t p = (size_t)(i - 1) * BB + b;
                int pg = tmode ? (int)t64p[p] : t32p[p];
                sc += trans[pg * NN + tg];
            }
        }
#pragma unroll
        for (int o = 16; o; o >>= 1) sc += __shfl_xor_sync(0xffffffffu, sc, o);

        if (lane == 0) { wred[w] = wpart; sred[w] = sc; }
        __syncthreads();
        if (tid == 0) {
            float wsum = wred[0] + wred[1];
            float logZ = C0 + 0.6931471805599453f * (float)stotal + __logf(wsum);
            int tg0 = tmode ? (int)t64p[b] : t32p[b];
            size_t li = (size_t)(len - 1) * BB + b;
            int tgl = tmode ? (int)t64p[li] : t32p[li];
            float score = sred[0] + sred[1] + strans[tg0] + etrans[tgl];
            g_partial[b] = logZ - score;
        }
        __syncthreads();                             // vbuf/wred safe for next phase
    }
#undef STEP_BODY

    // ---- last-CTA-done deterministic reduction ----
    __shared__ float rsh[64];
    __shared__ int islast;
    __threadfence();
    __syncthreads();
    if (tid == 0)
        islast = (atomicAdd(&g_count, 1) == GRID - 1);
    __syncthreads();
    if (islast) {
        __threadfence();
        float s = 0.f;
#pragma unroll
        for (int i = 0; i < BB / 64; i++)           // fixed order: deterministic
            s += g_partial[tid + i * 64];
        rsh[tid] = s;
        __syncthreads();
        for (int off = 32; off > 0; off >>= 1) {
            if (tid < off) rsh[tid] += rsh[tid + off];
            __syncthreads();
        }
        if (tid == 0) {
            out[0] = rsh[0] * (1.0f / BB);
            g_count = 0;                            // reset for next graph replay
        }
    }
}

extern "C" void kernel_launch(void* const* d_in, const int* in_sizes, int n_in,
                              void* d_out, int out_size) {
    const float* emit   = (const float*)d_in[0];
    const float* trans  = (const float*)d_in[1];
    const float* strans = (const float*)d_in[2];
    const float* etrans = (const float*)d_in[3];
    const void* target  = d_in[4];
    const void* mask    = d_in[5];

    len_kernel<<<BB / 4, 128>>>(mask);
    sort_kernel<<<1, BB>>>();
    crf_fused_kernel<<<GRID, 64>>>(emit, trans, strans, etrans, target,
                                   (float*)d_out);
}

// round 13
// speedup vs baseline: 1.5403x; 1.0564x over previous
#include <cuda_runtime.h>

#define TT 512
#define BB 1024
#define NN 64
#define GRID 512      // main kernel: one pair (2 batches) per 64-thread CTA
#define LGRID 64      // len kernel CTAs (8 rows each)

__device__ float g_partial[BB];
__device__ int g_len[BB];
__device__ int g_lenpart[LGRID][BB];
__device__ int g_pairs[2][BB / 2];
__device__ int g_count = 0;

typedef unsigned long long ull;

// ---- packed f32x2 helpers (Blackwell) ----
__device__ __forceinline__ ull pack2(float x, float y) {
    ull r; asm("mov.b64 %0, {%1, %2};" : "=l"(r) : "f"(x), "f"(y)); return r;
}
__device__ __forceinline__ void unpack2(ull v, float& x, float& y) {
    asm("mov.b64 {%0, %1}, %2;" : "=f"(x), "=f"(y) : "l"(v));
}
__device__ __forceinline__ ull fma2(ull a, ull b, ull c) {
    ull d; asm("fma.rn.f32x2 %0, %1, %2, %3;" : "=l"(d) : "l"(a), "l"(b), "l"(c)); return d;
}
__device__ __forceinline__ ull add2(ull a, ull b) {
    ull d; asm("add.rn.f32x2 %0, %1, %2;" : "=l"(d) : "l"(a), "l"(b)); return d;
}

__device__ __forceinline__ void cp_async4(unsigned smem_addr, const void* gptr) {
    asm volatile("cp.async.ca.shared.global [%0], [%1], 4;" :: "r"(smem_addr), "l"(gptr));
}
__device__ __forceinline__ void cp_commit() {
    asm volatile("cp.async.commit_group;");
}
__device__ __forceinline__ void cp_wait1() {
    asm volatile("cp.async.wait_group 1;");
}
__device__ __forceinline__ void cp_wait0() {
    asm volatile("cp.async.wait_group 0;");
}

// ------- kernel 1: coalesced per-CTA partial column sums of the mask -------
__global__ void __launch_bounds__(256) len_kernel(const void* __restrict__ mask_raw) {
    const int tid = threadIdx.x;
    const int c = blockIdx.x;                  // rows [8c, 8c+8)

    const unsigned char* m8 = (const unsigned char*)mask_raw;
    const int* m32 = (const int*)mask_raw;
    const float* mf = (const float*)mask_raw;
    int mmode;  // 0 = u8, 1 = i32, 2 = f32 (mask row 0 all-True since lengths >= 1)
    if (m8[0] == 1 && m8[1] == 1)      mmode = 0;
    else if (m8[0] == 1)               mmode = 1;
    else                               mmode = 2;

    int acc0 = 0, acc1 = 0, acc2 = 0, acc3 = 0;
#pragma unroll
    for (int r = 0; r < 8; r++) {
        const int row = c * 8 + r;
        if (mmode == 1) {
            acc0 += (m32[row * BB + tid]       != 0);
            acc1 += (m32[row * BB + tid + 256] != 0);
            acc2 += (m32[row * BB + tid + 512] != 0);
            acc3 += (m32[row * BB + tid + 768] != 0);
        } else if (mmode == 0) {
            acc0 += (m8[row * BB + tid]       != 0);
            acc1 += (m8[row * BB + tid + 256] != 0);
            acc2 += (m8[row * BB + tid + 512] != 0);
            acc3 += (m8[row * BB + tid + 768] != 0);
        } else {
            acc0 += (mf[row * BB + tid]       != 0.0f);
            acc1 += (mf[row * BB + tid + 256] != 0.0f);
            acc2 += (mf[row * BB + tid + 512] != 0.0f);
            acc3 += (mf[row * BB + tid + 768] != 0.0f);
        }
    }
    g_lenpart[c][tid]       = acc0;
    g_lenpart[c][tid + 256] = acc1;
    g_lenpart[c][tid + 512] = acc2;
    g_lenpart[c][tid + 768] = acc3;
}

// ------- kernel 2: sum partials, bitonic sort, complement pairing -------
__global__ void __launch_bounds__(BB) sort_kernel() {
    __shared__ int a[BB];
    const int tid = threadIdx.x;
    int len = 0;
#pragma unroll
    for (int c = 0; c < LGRID; c++) len += g_lenpart[c][tid];
    g_len[tid] = len;
    a[tid] = (len << 11) | tid;               // len<=512 (10 bits) | idx
    __syncthreads();
    for (int k = 2; k <= BB; k <<= 1) {
        for (int j = k >> 1; j > 0; j >>= 1) {
            int ixj = tid ^ j;
            if (ixj > tid) {
                bool up = (tid & k) == 0;
                int x = a[tid], y = a[ixj];
                if ((x > y) == up) { a[tid] = y; a[ixj] = x; }
            }
            __syncthreads();
        }
    }
    if (tid < BB / 2) {
        g_pairs[0][tid] = a[tid] & 0x7FF;               // short batch
        g_pairs[1][tid] = a[BB - 1 - tid] & 0x7FF;      // long batch
    }
}

// ---------------- kernel 3: fused forward + score + reduce ----------------
__global__ void __launch_bounds__(64, 8) crf_fused_kernel(
    const float* __restrict__ emit,
    const float* __restrict__ trans,
    const float* __restrict__ strans,
    const float* __restrict__ etrans,
    const void* __restrict__ target_raw,
    float* __restrict__ out)
{
    const int tid = threadIdx.x;          // 0..63
    const int lane = tid & 31;
    const int w = tid >> 5;
    const int k = tid;                    // this lane's state (0..63)
    const int pairid = blockIdx.x;

    __shared__ __align__(16) float vbuf[2][NN];   // double-buffered state exchange
    __shared__ float stagef[2][8][32];            // 8-slot cp.async ring per warp
    __shared__ float wred[2], sred[2];

    const int* t32p = (const int*)target_raw;
    int oddbits = 0;
#pragma unroll
    for (int i = 1; i < 16; i += 2) oddbits |= t32p[i];
    const int tmode = (oddbits == 0) ? 1 : 0;  // 1 = int64, 0 = int32
    const long long* t64p = (const long long*)target_raw;

    // E column for this lane's state, packed over j-pairs (64 regs)
    ull Ecol[32];
#pragma unroll
    for (int p = 0; p < 32; p++) {
        float t0 = trans[(2 * p) * NN + k];
        float t1 = trans[(2 * p + 1) * NN + k];
        Ecol[p] = pack2(__expf(t0), __expf(t1));
    }

    const unsigned stg0 = (unsigned)__cvta_generic_to_shared(&stagef[w][0][lane]);
#define STG(SLOT) (stg0 + (unsigned)(SLOT) * 128u)
#define LDSTAGE(DST, SLOT) \
    asm volatile("ld.shared.f32 %0, [%1];" : "=f"(DST) : "r"(STG(SLOT)))

    const float eet = __expf(etrans[k]);

// One forward step. NORM: apply 2^-s normalization (lag-1 ref read free from vv[0])
#define STEP_BODY(SLOT, PAR, NORM)                                              \
    {                                                                           \
        float e; LDSTAGE(e, SLOT);                                              \
        vbuf[PAR][k] = v;                                                       \
        __syncthreads();                                                        \
        const ulonglong2* vv = reinterpret_cast<const ulonglong2*>(vbuf[PAR]);  \
        ulonglong2 q0 = vv[0];                                                  \
        float m;                                                                \
        if (NORM) {                                                             \
            float rref, hi_; unpack2(q0.x, rref, hi_); (void)hi_;               \
            int sexp = ((__float_as_int(rref) >> 23) & 0xFF) - 127;             \
            stotal += sexp;                                                     \
            float scl = __int_as_float((127 - sexp) << 23);                     \
            m = __expf(e) * scl;                                                \
        } else {                                                                \
            m = __expf(e);                                                      \
        }                                                                       \
        ull c0 = 0, c1 = 0, c2 = 0, c3 = 0;                                     \
        {                                                                       \
            ulonglong2 q1 = vv[1];                                              \
            c0 = fma2(q0.x, Ecol[0], c0);                                       \
            c1 = fma2(q0.y, Ecol[1], c1);                                       \
            c2 = fma2(q1.x, Ecol[2], c2);                                       \
            c3 = fma2(q1.y, Ecol[3], c3);                                       \
        }                                                                       \
        _Pragma("unroll")                                                       \
        for (int p = 4; p < 32; p += 4) {                                       \
            ulonglong2 u0 = vv[p / 2], u1 = vv[p / 2 + 1];                      \
            c0 = fma2(u0.x, Ecol[p],     c0);                                   \
            c1 = fma2(u0.y, Ecol[p + 1], c1);                                   \
            c2 = fma2(u1.x, Ecol[p + 2], c2);                                   \
            c3 = fma2(u1.y, Ecol[p + 3], c3);                                   \
        }                                                                       \
        float cx, cy;                                                           \
        unpack2(add2(add2(c0, c1), add2(c2, c3)), cx, cy);                      \
        v = (cx + cy) * m;                                                      \
    }

    for (int ph = 0; ph < 2; ph++) {
        const int b = g_pairs[ph][pairid];
        const int len = g_len[b];
        const float* bp = emit + b * NN + k;     // row stride = BB*NN = 65536 floats

        // init: alpha(0)_k = strans[k] + emit[0][b][k]; offset C0 = alpha(0)_0
        const float C0 = strans[0] + emit[b * NN];
        float v = __expf(strans[k] + bp[0] - C0);
        int stotal = 0;

        cp_wait0();                              // drain ring before reuse
        __syncthreads();
        // prologue: G0 = steps 1..4 (slots 0..3), G1 = steps 5..8 (slots 4..7)
#pragma unroll
        for (int j = 0; j < 4; j++)
            cp_async4(STG(j), bp + (size_t)min(1 + j, TT - 1) * (BB * NN));
        cp_commit();
#pragma unroll
        for (int j = 0; j < 4; j++)
            cp_async4(STG(4 + j), bp + (size_t)min(5 + j, TT - 1) * (BB * NN));
        cp_commit();

        int pb = 0;                              // ring half being consumed
        int t = 1;
        for (; t + 4 <= len; t += 4) {           // t odd: parities 1,0,1,0
            cp_wait1();                          // current half's group complete
            const int ro = pb << 2;
            STEP_BODY(ro + 0, 1, true);
            STEP_BODY(ro + 1, 0, false);
            STEP_BODY(ro + 2, 1, false);
            STEP_BODY(ro + 3, 0, false);
            // refill freed half with steps t+8..t+11
#pragma unroll
            for (int j = 0; j < 4; j++)
                cp_async4(STG(ro + j), bp + (size_t)min(t + 8 + j, TT - 1) * (BB * NN));
            cp_commit();
            pb ^= 1;
        }
        cp_wait0();
        for (; t < len; t++) {                   // tail: data already staged
            const int slot = (t - 1) & 7, par = t & 1;
            STEP_BODY(slot, par, true);
        }

        // logZ partial
        float wpart = v * eet;
#pragma unroll
        for (int o = 16; o; o >>= 1) wpart += __shfl_xor_sync(0xffffffffu, wpart, o);

        // gold score: 64-lane strided over timesteps
        float sc = 0.f;
        for (int i = tid; i < len; i += 64) {
            size_t idx = (size_t)i * BB + b;
            int tg = tmode ? (int)t64p[idx] : t32p[idx];
            sc += emit[idx * NN + tg];
            if (i > 0) {
                size_t p = (size_t)(i - 1) * BB + b;
                int pg = tmode ? (int)t64p[p] : t32p[p];
                sc += trans[pg * NN + tg];
            }
        }
#pragma unroll
        for (int o = 16; o; o >>= 1) sc += __shfl_xor_sync(0xffffffffu, sc, o);

        if (lane == 0) { wred[w] = wpart; sred[w] = sc; }
        __syncthreads();
        if (tid == 0) {
            float wsum = wred[0] + wred[1];
            float logZ = C0 + 0.6931471805599453f * (float)stotal + __logf(wsum);
            int tg0 = tmode ? (int)t64p[b] : t32p[b];
            size_t li = (size_t)(len - 1) * BB + b;
            int tgl = tmode ? (int)t64p[li] : t32p[li];
            float score = sred[0] + sred[1] + strans[tg0] + etrans[tgl];
            g_partial[b] = logZ - score;
        }
        __syncthreads();
    }
#undef STEP_BODY
#undef LDSTAGE
#undef STG

    // ---- last-CTA-done deterministic reduction ----
    __shared__ float rsh[64];
    __shared__ int islast;
    __threadfence();
    __syncthreads();
    if (tid == 0)
        islast = (atomicAdd(&g_count, 1) == GRID - 1);
    __syncthreads();
    if (islast) {
        __threadfence();
        float s = 0.f;
#pragma unroll
        for (int i = 0; i < BB / 64; i++)       // fixed order: deterministic
            s += g_partial[tid + i * 64];
        rsh[tid] = s;
        __syncthreads();
        for (int off = 32; off > 0; off >>= 1) {
            if (tid < off) rsh[tid] += rsh[tid + off];
            __syncthreads();
        }
        if (tid == 0) {
            out[0] = rsh[0] * (1.0f / BB);
            g_count = 0;                        // reset for next graph replay
        }
    }
}

extern "C" void kernel_launch(void* const* d_in, const int* in_sizes, int n_in,
                              void* d_out, int out_size) {
    const float* emit   = (const float*)d_in[0];
    const float* trans  = (const float*)d_in[1];
    const float* strans = (const float*)d_in[2];
    const float* etrans = (const float*)d_in[3];
    const void* target  = d_in[4];
    const void* mask    = d_in[5];

    len_kernel<<<LGRID, 256>>>(mask);
    sort_kernel<<<1, BB>>>();
    crf_fused_kernel<<<GRID, 64>>>(emit, trans, strans, etrans, target,
                                   (float*)d_out);
}